// round 6
// baseline (speedup 1.0000x reference)
#include <cuda_runtime.h>
#include <math.h>

// ---------------------------------------------------------------------------
// GCN 2-layer: out = sigmoid( S*( relu( S*X*W0 + b0 ) * W1 ) + b1 )
// S = D^-1/2 (A + I) D^-1/2,  S*(X W) = (S X) W.
//   layer1: agg0 = S*X  (CSR gather, 64f) -> h = relu(agg0*W0 + b0)
//   layer2: hw = h*W1  (GEMM first)       -> out = sigmoid(S*hw + b1) (fused)
// CSR build per launch: degree count -> prefix scan -> fill (src,norm) perm.
// Gather (pull) instead of scatter atomics: each dst row written exactly once.
// ---------------------------------------------------------------------------

#define NN 100000
#define EE 1600000

__device__ int   g_is_i32;
__device__ int   g_deg[NN];
__device__ float g_dis[NN];
__device__ int   g_row[NN + 1];
__device__ int   g_cursor[NN];
__device__ int   g_psrc[EE];
__device__ float g_pnorm[EE];
__device__ float g_agg0[(size_t)NN * 64];   // S*X
__device__ float g_h[(size_t)NN * 128];     // relu(agg0*W0+b0)
__device__ float g_hw[(size_t)NN * 64];     // h*W1

// --- dtype detection: jax without x64 silently downcasts int64 -> int32 ----
__global__ void k_detect(const void* ei, int n, int e) {
    __shared__ int bad;
    if (threadIdx.x == 0) bad = 0;
    __syncthreads();
    const long long* p = (const long long*)ei;
    int cnt = e < 2048 ? e : 2048;
    int mybad = 0;
    for (int i = threadIdx.x; i < cnt; i += blockDim.x) {
        long long v = p[i];
        if (v < 0 || v >= (long long)n) mybad = 1;
    }
    if (mybad) atomicOr(&bad, 1);
    __syncthreads();
    if (threadIdx.x == 0) g_is_i32 = bad;  // bad int64 values => data is int32
}

__global__ void k_init_deg(int n) {
    int i = blockIdx.x * blockDim.x + threadIdx.x;
    if (i < n) g_deg[i] = 1;  // self loop
}

__global__ void k_count_deg(const void* ei, int E) {
    int e = blockIdx.x * blockDim.x + threadIdx.x;
    if (e >= E) return;
    int ii = g_is_i32;
    int d = ii ? ((const int*)ei)[E + e] : (int)((const long long*)ei)[E + e];
    atomicAdd(&g_deg[d], 1);
}

__global__ void k_dis(int n) {
    int i = blockIdx.x * blockDim.x + threadIdx.x;
    if (i < n) g_dis[i] = rsqrtf((float)g_deg[i]);
}

// Single-block hierarchical exclusive scan of (deg-1) over N nodes.
#define SCAN_T 1024
__global__ __launch_bounds__(SCAN_T) void k_scan(int N) {
    __shared__ int ssum[SCAN_T];
    int t = threadIdx.x;
    int per = (N + SCAN_T - 1) / SCAN_T;
    int beg = t * per;
    int end = beg + per; if (end > N) end = N;
    int sum = 0;
    for (int i = beg; i < end; i++) sum += g_deg[i] - 1;
    ssum[t] = sum;
    __syncthreads();
    for (int off = 1; off < SCAN_T; off <<= 1) {
        int v = (t >= off) ? ssum[t - off] : 0;
        __syncthreads();
        ssum[t] += v;
        __syncthreads();
    }
    int run = (t == 0) ? 0 : ssum[t - 1];
    for (int i = beg; i < end; i++) {
        g_row[i] = run;
        g_cursor[i] = run;
        run += g_deg[i] - 1;
    }
    if (t == SCAN_T - 1) g_row[N] = run;
}

__global__ void k_fill(const void* ei, int E) {
    int e = blockIdx.x * blockDim.x + threadIdx.x;
    if (e >= E) return;
    int ii = g_is_i32;
    int s, d;
    if (ii) {
        s = ((const int*)ei)[e];
        d = ((const int*)ei)[E + e];
    } else {
        s = (int)((const long long*)ei)[e];
        d = (int)((const long long*)ei)[E + e];
    }
    float nr = g_dis[s] * g_dis[d];
    int pos = atomicAdd(&g_cursor[d], 1);
    g_psrc[pos] = s;
    g_pnorm[pos] = nr;
}

// agg0[d] = dis[d]^2 * x[d] + sum_{edges into d} norm * x[src]
// One 16-thread group per dst node (16 float4 = 64 feats).
__global__ __launch_bounds__(256) void k_agg1(const float4* __restrict__ x4, int N) {
    int gid = blockIdx.x * 16 + (threadIdx.x >> 4);
    if (gid >= N) return;
    int lane = threadIdx.x & 15;
    float d1 = g_dis[gid];
    float dd = d1 * d1;
    float4 sv = x4[gid * 16 + lane];
    float4 acc = make_float4(sv.x * dd, sv.y * dd, sv.z * dd, sv.w * dd);
    int j = g_row[gid], end = g_row[gid + 1];
    for (; j + 4 <= end; j += 4) {
        int s0 = g_psrc[j], s1 = g_psrc[j + 1], s2 = g_psrc[j + 2], s3 = g_psrc[j + 3];
        float w0 = g_pnorm[j], w1 = g_pnorm[j + 1], w2 = g_pnorm[j + 2], w3 = g_pnorm[j + 3];
        float4 v0 = x4[s0 * 16 + lane];
        float4 v1 = x4[s1 * 16 + lane];
        float4 v2 = x4[s2 * 16 + lane];
        float4 v3 = x4[s3 * 16 + lane];
        acc.x += w0 * v0.x + w1 * v1.x + w2 * v2.x + w3 * v3.x;
        acc.y += w0 * v0.y + w1 * v1.y + w2 * v2.y + w3 * v3.y;
        acc.z += w0 * v0.z + w1 * v1.z + w2 * v2.z + w3 * v3.z;
        acc.w += w0 * v0.w + w1 * v1.w + w2 * v2.w + w3 * v3.w;
    }
    for (; j < end; j++) {
        int s = g_psrc[j];
        float w = g_pnorm[j];
        float4 v = x4[s * 16 + lane];
        acc.x += w * v.x; acc.y += w * v.y; acc.z += w * v.z; acc.w += w * v.w;
    }
    ((float4*)g_agg0)[gid * 16 + lane] = acc;
}

// h = relu(agg0 * W0 + b0)   [N,64] x [64,128]
__global__ __launch_bounds__(256) void k_gemm1(const float* __restrict__ W,
                                               const float* __restrict__ bias,
                                               int N) {
    __shared__ float As[64][64];    // [k][m]
    __shared__ float Bs[64][128];   // [k][n]
    int t = threadIdx.x;
    int mb = blockIdx.x * 64;
    {
        int rl = t >> 4;
        int kq = (t & 15) * 4;
#pragma unroll
        for (int r = 0; r < 4; r++) {
            int row = rl + r * 16;
            int grow = mb + row;
            float4 v = make_float4(0.f, 0.f, 0.f, 0.f);
            if (grow < N) v = *(const float4*)(g_agg0 + (size_t)grow * 64 + kq);
            As[kq + 0][row] = v.x; As[kq + 1][row] = v.y;
            As[kq + 2][row] = v.z; As[kq + 3][row] = v.w;
        }
    }
    {
        const float4* W4 = (const float4*)W;
#pragma unroll
        for (int i = 0; i < 8; i++) {
            int q = t + i * 256;      // 0..2047
            int k = q >> 5, n4 = q & 31;
            ((float4*)&Bs[k][0])[n4] = W4[q];
        }
    }
    __syncthreads();
    int m0 = (t >> 4) * 4, n0 = (t & 15) * 8;
    float acc[4][8];
#pragma unroll
    for (int i = 0; i < 4; i++)
#pragma unroll
        for (int j = 0; j < 8; j++) acc[i][j] = 0.f;
#pragma unroll 8
    for (int k = 0; k < 64; k++) {
        float4 a = *(const float4*)&As[k][m0];
        float4 bA = *(const float4*)&Bs[k][n0];
        float4 bB = *(const float4*)&Bs[k][n0 + 4];
        float av[4] = {a.x, a.y, a.z, a.w};
        float bv[8] = {bA.x, bA.y, bA.z, bA.w, bB.x, bB.y, bB.z, bB.w};
#pragma unroll
        for (int i = 0; i < 4; i++)
#pragma unroll
            for (int j = 0; j < 8; j++) acc[i][j] += av[i] * bv[j];
    }
    float bb[8];
#pragma unroll
    for (int j = 0; j < 8; j++) bb[j] = bias[n0 + j];
#pragma unroll
    for (int i = 0; i < 4; i++) {
        int grow = mb + m0 + i;
        if (grow < N) {
            float4 o1, o2;
            o1.x = fmaxf(acc[i][0] + bb[0], 0.f);
            o1.y = fmaxf(acc[i][1] + bb[1], 0.f);
            o1.z = fmaxf(acc[i][2] + bb[2], 0.f);
            o1.w = fmaxf(acc[i][3] + bb[3], 0.f);
            o2.x = fmaxf(acc[i][4] + bb[4], 0.f);
            o2.y = fmaxf(acc[i][5] + bb[5], 0.f);
            o2.z = fmaxf(acc[i][6] + bb[6], 0.f);
            o2.w = fmaxf(acc[i][7] + bb[7], 0.f);
            *(float4*)(g_h + (size_t)grow * 128 + n0) = o1;
            *(float4*)(g_h + (size_t)grow * 128 + n0 + 4) = o2;
        }
    }
}

// hw = h * W1   [N,128] x [128,64]
__global__ __launch_bounds__(256) void k_gemm2(const float* __restrict__ W, int N) {
    __shared__ float As[64][64];   // [k][m]
    __shared__ float Bs[64][64];   // [k][n]
    int t = threadIdx.x;
    int mb = blockIdx.x * 64;
    int m0 = (t >> 4) * 4, n0 = (t & 15) * 4;
    float acc[4][4];
#pragma unroll
    for (int i = 0; i < 4; i++)
#pragma unroll
        for (int j = 0; j < 4; j++) acc[i][j] = 0.f;

    for (int kc = 0; kc < 2; kc++) {
        {
            int rl = t >> 4;
            int kq = (t & 15) * 4;
#pragma unroll
            for (int r = 0; r < 4; r++) {
                int row = rl + r * 16;
                int grow = mb + row;
                float4 v = make_float4(0.f, 0.f, 0.f, 0.f);
                if (grow < N) v = *(const float4*)(g_h + (size_t)grow * 128 + kc * 64 + kq);
                As[kq + 0][row] = v.x; As[kq + 1][row] = v.y;
                As[kq + 2][row] = v.z; As[kq + 3][row] = v.w;
            }
        }
        {
            const float4* W4 = (const float4*)(W + kc * 64 * 64);
#pragma unroll
            for (int i = 0; i < 4; i++) {
                int q = t + i * 256;   // 0..1023
                int k = q >> 4, n4 = q & 15;
                ((float4*)&Bs[k][0])[n4] = W4[q];
            }
        }
        __syncthreads();
#pragma unroll 8
        for (int k = 0; k < 64; k++) {
            float4 a = *(const float4*)&As[k][m0];
            float4 b = *(const float4*)&Bs[k][n0];
            float av[4] = {a.x, a.y, a.z, a.w};
            float bv[4] = {b.x, b.y, b.z, b.w};
#pragma unroll
            for (int i = 0; i < 4; i++)
#pragma unroll
                for (int j = 0; j < 4; j++) acc[i][j] += av[i] * bv[j];
        }
        __syncthreads();
    }
#pragma unroll
    for (int i = 0; i < 4; i++) {
        int grow = mb + m0 + i;
        if (grow < N)
            *(float4*)(g_hw + (size_t)grow * 64 + n0) =
                make_float4(acc[i][0], acc[i][1], acc[i][2], acc[i][3]);
    }
}

// out[d] = sigmoid( dis[d]^2*hw[d] + sum norm*hw[src] + b1 )
__global__ __launch_bounds__(256) void k_agg2(float4* __restrict__ out4,
                                              const float4* __restrict__ b1_4, int N) {
    int gid = blockIdx.x * 16 + (threadIdx.x >> 4);
    if (gid >= N) return;
    int lane = threadIdx.x & 15;
    const float4* hw4 = (const float4*)g_hw;
    float d1 = g_dis[gid];
    float dd = d1 * d1;
    float4 sv = hw4[gid * 16 + lane];
    float4 acc = make_float4(sv.x * dd, sv.y * dd, sv.z * dd, sv.w * dd);
    int j = g_row[gid], end = g_row[gid + 1];
    for (; j + 4 <= end; j += 4) {
        int s0 = g_psrc[j], s1 = g_psrc[j + 1], s2 = g_psrc[j + 2], s3 = g_psrc[j + 3];
        float w0 = g_pnorm[j], w1 = g_pnorm[j + 1], w2 = g_pnorm[j + 2], w3 = g_pnorm[j + 3];
        float4 v0 = hw4[s0 * 16 + lane];
        float4 v1 = hw4[s1 * 16 + lane];
        float4 v2 = hw4[s2 * 16 + lane];
        float4 v3 = hw4[s3 * 16 + lane];
        acc.x += w0 * v0.x + w1 * v1.x + w2 * v2.x + w3 * v3.x;
        acc.y += w0 * v0.y + w1 * v1.y + w2 * v2.y + w3 * v3.y;
        acc.z += w0 * v0.z + w1 * v1.z + w2 * v2.z + w3 * v3.z;
        acc.w += w0 * v0.w + w1 * v1.w + w2 * v2.w + w3 * v3.w;
    }
    for (; j < end; j++) {
        int s = g_psrc[j];
        float w = g_pnorm[j];
        float4 v = hw4[s * 16 + lane];
        acc.x += w * v.x; acc.y += w * v.y; acc.z += w * v.z; acc.w += w * v.w;
    }
    float4 bb = b1_4[lane];
    float4 o;
    o.x = 1.f / (1.f + __expf(-(acc.x + bb.x)));
    o.y = 1.f / (1.f + __expf(-(acc.y + bb.y)));
    o.z = 1.f / (1.f + __expf(-(acc.z + bb.z)));
    o.w = 1.f / (1.f + __expf(-(acc.w + bb.w)));
    out4[gid * 16 + lane] = o;
}

extern "C" void kernel_launch(void* const* d_in, const int* in_sizes, int n_in,
                              void* d_out, int out_size) {
    const float* x  = (const float*)d_in[0];
    const void*  ei = d_in[1];
    const float* W0 = (const float*)d_in[2];
    const float* b0 = (const float*)d_in[3];
    const float* W1 = (const float*)d_in[4];
    const float* b1 = (const float*)d_in[5];
    float* out = (float*)d_out;

    int N = in_sizes[0] / 64;       // 100000
    int E = in_sizes[1] / 2;        // 1600000

    const int T = 256;
    k_detect<<<1, T>>>(ei, N, E);
    k_init_deg<<<(N + T - 1) / T, T>>>(N);
    k_count_deg<<<(E + T - 1) / T, T>>>(ei, E);
    k_dis<<<(N + T - 1) / T, T>>>(N);
    k_scan<<<1, SCAN_T>>>(N);
    k_fill<<<(E + T - 1) / T, T>>>(ei, E);

    int gblocks = (N + 15) / 16;
    k_agg1<<<gblocks, 256>>>((const float4*)x, N);
    k_gemm1<<<(N + 63) / 64, 256>>>(W0, b0, N);
    k_gemm2<<<(N + 63) / 64, 256>>>(W1, N);
    k_agg2<<<gblocks, 256>>>((float4*)out, (const float4*)b1, N);
}

// round 9
// speedup vs baseline: 1.4167x; 1.4167x over previous
#include <cuda_runtime.h>
#include <math.h>

// ---------------------------------------------------------------------------
// GCN 2-layer: out = sigmoid( S*( relu( S*X*W0 + b0 ) * W1 ) + b1 )
// S = D^-1/2 (A + I) D^-1/2,  S*(X W) = (S X) W.
// Aggregation: parallel-over-edges scatter with red.global.add.v4.f32
// (measured best: 358.8us vs 412us for CSR gather).
// GEMMs: tf32 mma.sync tensor cores, f32 accumulate.
// ---------------------------------------------------------------------------

#define NN 100000
#define EE 1600000

__device__ int   g_is_i32;
__device__ int   g_deg[NN];
__device__ float g_dis[NN];
__device__ int   g_src[EE];
__device__ int   g_dst[EE];
__device__ float g_norm[EE];
__device__ float g_agg0[(size_t)NN * 64];   // S*X
__device__ float g_h[(size_t)NN * 128];     // relu(agg0*W0+b0)
__device__ float g_hw[(size_t)NN * 64];     // h*W1

// --- dtype detection: jax without x64 silently downcasts int64 -> int32 ----
__global__ void k_detect(const void* ei, int n, int e) {
    __shared__ int bad;
    if (threadIdx.x == 0) bad = 0;
    __syncthreads();
    const long long* p = (const long long*)ei;
    int cnt = e < 2048 ? e : 2048;
    int mybad = 0;
    for (int i = threadIdx.x; i < cnt; i += blockDim.x) {
        long long v = p[i];
        if (v < 0 || v >= (long long)n) mybad = 1;
    }
    if (mybad) atomicOr(&bad, 1);
    __syncthreads();
    if (threadIdx.x == 0) g_is_i32 = bad;
}

__global__ void k_init_deg(int n) {
    int i = blockIdx.x * blockDim.x + threadIdx.x;
    if (i < n) g_deg[i] = 1;  // self loop
}

__global__ void k_count_deg(const void* ei, int E) {
    int e = blockIdx.x * blockDim.x + threadIdx.x;
    if (e >= E) return;
    int ii = g_is_i32;
    int d = ii ? ((const int*)ei)[E + e] : (int)((const long long*)ei)[E + e];
    atomicAdd(&g_deg[d], 1);
}

__global__ void k_dis(int n) {
    int i = blockIdx.x * blockDim.x + threadIdx.x;
    if (i < n) g_dis[i] = rsqrtf((float)g_deg[i]);
}

__global__ void k_prep(const void* ei, int E) {
    int e = blockIdx.x * blockDim.x + threadIdx.x;
    if (e >= E) return;
    int ii = g_is_i32;
    int s, d;
    if (ii) {
        s = ((const int*)ei)[e];
        d = ((const int*)ei)[E + e];
    } else {
        s = (int)((const long long*)ei)[e];
        d = (int)((const long long*)ei)[E + e];
    }
    g_src[e] = s;
    g_dst[e] = d;
    g_norm[e] = g_dis[s] * g_dis[d];
}

// agg0 = dis^2 * x   (self-loop term), then scatter adds the rest
__global__ void k_self1(const float4* __restrict__ x4, int n16) {
    int g = blockIdx.x * blockDim.x + threadIdx.x;
    if (g >= n16) return;
    int row = g >> 4;
    float d2 = g_dis[row] * g_dis[row];
    float4 v = x4[g];
    ((float4*)g_agg0)[g] = make_float4(v.x * d2, v.y * d2, v.z * d2, v.w * d2);
}

__global__ __launch_bounds__(256) void k_scat1(const float4* __restrict__ x4, int total) {
    int g = blockIdx.x * blockDim.x + threadIdx.x;
    if (g >= total) return;
    int e = g >> 4, f = g & 15;
    int s = g_src[e], d = g_dst[e];
    float nr = g_norm[e];
    float4 v = x4[s * 16 + f];
    float4* p = ((float4*)g_agg0) + (d * 16 + f);
    asm volatile("red.global.add.v4.f32 [%0], {%1,%2,%3,%4};"
                 :: "l"(p), "f"(v.x * nr), "f"(v.y * nr), "f"(v.z * nr), "f"(v.w * nr)
                 : "memory");
}

// ------------------------ tf32 tensor-core GEMMs ---------------------------

__device__ __forceinline__ unsigned tf32_of(float f) {
    unsigned r;
    asm("cvt.rna.tf32.f32 %0, %1;" : "=r"(r) : "f"(f));
    return r;
}

__device__ __forceinline__ void mma_tf32(float* c,
                                         unsigned a0, unsigned a1, unsigned a2, unsigned a3,
                                         unsigned b0, unsigned b1) {
    asm volatile(
        "mma.sync.aligned.m16n8k8.row.col.f32.tf32.tf32.f32 "
        "{%0,%1,%2,%3}, {%4,%5,%6,%7}, {%8,%9}, {%0,%1,%2,%3};"
        : "+f"(c[0]), "+f"(c[1]), "+f"(c[2]), "+f"(c[3])
        : "r"(a0), "r"(a1), "r"(a2), "r"(a3), "r"(b0), "r"(b1));
}

// h = relu(agg0[N,64] * W0[64,128] + b0).  Block: 32 rows.  8 warps.
__global__ __launch_bounds__(256) void k_gemm1(const float* __restrict__ W,
                                               const float* __restrict__ bias, int N) {
    __shared__ unsigned As[32][68];    // [m][k], pad 4 -> conflict-free frags
    __shared__ unsigned Ws[64][132];   // [k][n], pad 4
    int t = threadIdx.x;
    int mb = blockIdx.x * 32;
    {   // load A tile (32x64)
        int r = t >> 3;
        int q = (t & 7) * 2;           // float4 quad index
        int grow = mb + r;
        float4 v0 = make_float4(0.f, 0.f, 0.f, 0.f), v1 = v0;
        if (grow < N) {
            const float* base = g_agg0 + (size_t)grow * 64 + q * 4;
            v0 = *(const float4*)base;
            v1 = *(const float4*)(base + 4);
        }
        int c = q * 4;
        As[r][c + 0] = tf32_of(v0.x); As[r][c + 1] = tf32_of(v0.y);
        As[r][c + 2] = tf32_of(v0.z); As[r][c + 3] = tf32_of(v0.w);
        As[r][c + 4] = tf32_of(v1.x); As[r][c + 5] = tf32_of(v1.y);
        As[r][c + 6] = tf32_of(v1.z); As[r][c + 7] = tf32_of(v1.w);
    }
    {   // load W0 (64x128)
        const float4* W4 = (const float4*)W;
#pragma unroll
        for (int i = 0; i < 8; i++) {
            int q = t + i * 256;        // 0..2047
            int r = q >> 5, c = (q & 31) * 4;
            float4 v = W4[q];
            Ws[r][c + 0] = tf32_of(v.x); Ws[r][c + 1] = tf32_of(v.y);
            Ws[r][c + 2] = tf32_of(v.z); Ws[r][c + 3] = tf32_of(v.w);
        }
    }
    __syncthreads();
    int w = t >> 5, lane = t & 31;
    int g = lane >> 2, tg = lane & 3;
    int mr = (w & 1) * 16;             // 2 m-tiles of 16
    int nb = (w >> 1) * 32;            // 4 n-blocks of 32 (4 n8-tiles each)
    float acc[4][4];
#pragma unroll
    for (int i = 0; i < 4; i++)
#pragma unroll
        for (int j = 0; j < 4; j++) acc[i][j] = 0.f;
#pragma unroll
    for (int k0 = 0; k0 < 64; k0 += 8) {
        unsigned a0 = As[mr + g][k0 + tg];
        unsigned a1 = As[mr + g + 8][k0 + tg];
        unsigned a2 = As[mr + g][k0 + tg + 4];
        unsigned a3 = As[mr + g + 8][k0 + tg + 4];
#pragma unroll
        for (int nt = 0; nt < 4; nt++) {
            int n0 = nb + nt * 8;
            unsigned b0 = Ws[k0 + tg][n0 + g];
            unsigned b1 = Ws[k0 + tg + 4][n0 + g];
            mma_tf32(acc[nt], a0, a1, a2, a3, b0, b1);
        }
    }
#pragma unroll
    for (int nt = 0; nt < 4; nt++) {
        int col = nb + nt * 8 + 2 * tg;
        float bx = bias[col], by = bias[col + 1];
        int r0 = mb + mr + g, r1 = r0 + 8;
        if (r0 < N) {
            float2 o;
            o.x = fmaxf(acc[nt][0] + bx, 0.f);
            o.y = fmaxf(acc[nt][1] + by, 0.f);
            *(float2*)(g_h + (size_t)r0 * 128 + col) = o;
        }
        if (r1 < N) {
            float2 o;
            o.x = fmaxf(acc[nt][2] + bx, 0.f);
            o.y = fmaxf(acc[nt][3] + by, 0.f);
            *(float2*)(g_h + (size_t)r1 * 128 + col) = o;
        }
    }
}

// hw = h[N,128] * W1[128,64].  Block: 32 rows, K chunked 2x64.
__global__ __launch_bounds__(256) void k_gemm2(const float* __restrict__ W, int N) {
    __shared__ unsigned As[32][68];
    __shared__ unsigned Ws[64][68];
    int t = threadIdx.x;
    int mb = blockIdx.x * 32;
    int w = t >> 5, lane = t & 31;
    int g = lane >> 2, tg = lane & 3;
    int mr = (w & 1) * 16;
    int nb = (w >> 1) * 16;            // 4 n-blocks of 16 (2 n8-tiles each)
    float acc[2][4];
#pragma unroll
    for (int i = 0; i < 2; i++)
#pragma unroll
        for (int j = 0; j < 4; j++) acc[i][j] = 0.f;

    for (int kc = 0; kc < 2; kc++) {
        {   // load A chunk (32x64)
            int r = t >> 3;
            int q = (t & 7) * 2;
            int grow = mb + r;
            float4 v0 = make_float4(0.f, 0.f, 0.f, 0.f), v1 = v0;
            if (grow < N) {
                const float* base = g_h + (size_t)grow * 128 + kc * 64 + q * 4;
                v0 = *(const float4*)base;
                v1 = *(const float4*)(base + 4);
            }
            int c = q * 4;
            As[r][c + 0] = tf32_of(v0.x); As[r][c + 1] = tf32_of(v0.y);
            As[r][c + 2] = tf32_of(v0.z); As[r][c + 3] = tf32_of(v0.w);
            As[r][c + 4] = tf32_of(v1.x); As[r][c + 5] = tf32_of(v1.y);
            As[r][c + 6] = tf32_of(v1.z); As[r][c + 7] = tf32_of(v1.w);
        }
        {   // load W1 chunk (64x64)
            const float4* W4 = (const float4*)(W + kc * 64 * 64);
#pragma unroll
            for (int i = 0; i < 4; i++) {
                int q = t + i * 256;    // 0..1023
                int r = q >> 4, c = (q & 15) * 4;
                float4 v = W4[q];
                Ws[r][c + 0] = tf32_of(v.x); Ws[r][c + 1] = tf32_of(v.y);
                Ws[r][c + 2] = tf32_of(v.z); Ws[r][c + 3] = tf32_of(v.w);
            }
        }
        __syncthreads();
#pragma unroll
        for (int k0 = 0; k0 < 64; k0 += 8) {
            unsigned a0 = As[mr + g][k0 + tg];
            unsigned a1 = As[mr + g + 8][k0 + tg];
            unsigned a2 = As[mr + g][k0 + tg + 4];
            unsigned a3 = As[mr + g + 8][k0 + tg + 4];
#pragma unroll
            for (int nt = 0; nt < 2; nt++) {
                int n0 = nb + nt * 8;
                unsigned b0 = Ws[k0 + tg][n0 + g];
                unsigned b1 = Ws[k0 + tg + 4][n0 + g];
                mma_tf32(acc[nt], a0, a1, a2, a3, b0, b1);
            }
        }
        __syncthreads();
    }
#pragma unroll
    for (int nt = 0; nt < 2; nt++) {
        int col = nb + nt * 8 + 2 * tg;
        int r0 = mb + mr + g, r1 = r0 + 8;
        if (r0 < N)
            *(float2*)(g_hw + (size_t)r0 * 64 + col) = make_float2(acc[nt][0], acc[nt][1]);
        if (r1 < N)
            *(float2*)(g_hw + (size_t)r1 * 64 + col) = make_float2(acc[nt][2], acc[nt][3]);
    }
}

// out = dis^2 * hw  (self-loop), then scatter adds the rest
__global__ void k_self2(float4* __restrict__ out4, int n16) {
    int g = blockIdx.x * blockDim.x + threadIdx.x;
    if (g >= n16) return;
    int row = g >> 4;
    float d2 = g_dis[row] * g_dis[row];
    float4 v = ((const float4*)g_hw)[g];
    out4[g] = make_float4(v.x * d2, v.y * d2, v.z * d2, v.w * d2);
}

__global__ __launch_bounds__(256) void k_scat2(float4* __restrict__ out4, int total) {
    int g = blockIdx.x * blockDim.x + threadIdx.x;
    if (g >= total) return;
    int e = g >> 4, f = g & 15;
    int s = g_src[e], d = g_dst[e];
    float nr = g_norm[e];
    float4 v = ((const float4*)g_hw)[s * 16 + f];
    float4* p = out4 + (d * 16 + f);
    asm volatile("red.global.add.v4.f32 [%0], {%1,%2,%3,%4};"
                 :: "l"(p), "f"(v.x * nr), "f"(v.y * nr), "f"(v.z * nr), "f"(v.w * nr)
                 : "memory");
}

__global__ void k_fin(float4* __restrict__ out4, const float4* __restrict__ b1, int n16) {
    int g = blockIdx.x * blockDim.x + threadIdx.x;
    if (g >= n16) return;
    float4 v = out4[g];
    float4 bb = b1[g & 15];
    v.x = 1.f / (1.f + __expf(-(v.x + bb.x)));
    v.y = 1.f / (1.f + __expf(-(v.y + bb.y)));
    v.z = 1.f / (1.f + __expf(-(v.z + bb.z)));
    v.w = 1.f / (1.f + __expf(-(v.w + bb.w)));
    out4[g] = v;
}

extern "C" void kernel_launch(void* const* d_in, const int* in_sizes, int n_in,
                              void* d_out, int out_size) {
    const float* x  = (const float*)d_in[0];
    const void*  ei = d_in[1];
    const float* W0 = (const float*)d_in[2];
    const float* b0 = (const float*)d_in[3];
    const float* W1 = (const float*)d_in[4];
    const float* b1 = (const float*)d_in[5];
    float* out = (float*)d_out;

    int N = in_sizes[0] / 64;       // 100000
    int E = in_sizes[1] / 2;        // 1600000
    int n16 = N * 16;
    int e16 = E * 16;

    const int T = 256;
    k_detect<<<1, T>>>(ei, N, E);
    k_init_deg<<<(N + T - 1) / T, T>>>(N);
    k_count_deg<<<(E + T - 1) / T, T>>>(ei, E);
    k_dis<<<(N + T - 1) / T, T>>>(N);
    k_prep<<<(E + T - 1) / T, T>>>(ei, E);

    k_self1<<<(n16 + T - 1) / T, T>>>((const float4*)x, n16);
    k_scat1<<<(e16 + T - 1) / T, T>>>((const float4*)x, e16);
    k_gemm1<<<(N + 31) / 32, 256>>>(W0, b0, N);
    k_gemm2<<<(N + 31) / 32, 256>>>(W1, N);
    k_self2<<<(n16 + T - 1) / T, T>>>((float4*)out, n16);
    k_scat2<<<(e16 + T - 1) / T, T>>>((float4*)out, e16);
    k_fin<<<(n16 + T - 1) / T, T>>>((float4*)out, (const float4*)b1, n16);
}